// round 7
// baseline (speedup 1.0000x reference)
#include <cuda_runtime.h>
#include <math.h>

#define N_PTS 65536
#define KKEY 64
#define NT 256
#define GRID 128

typedef unsigned long long u64;

// scratch (no allocations allowed) — referenced ONLY from device code
__device__ u64 g_keys[N_PTS];
__device__ u64 g_cand[64 * KKEY];   // 4096
__device__ u64 g_cand2[4 * KKEY];   // 256
__device__ unsigned g_ctr1, g_ctr2, g_ctr3;   // zero-init; reset at kernel end

// ---------------------------------------------------------------------------
// packed f32x2 helpers (FFMA2: 2 fp32 FMAs per instruction, only via PTX)
// ---------------------------------------------------------------------------
__device__ __forceinline__ u64 fma2(u64 a, u64 b, u64 c) {
    u64 d;
    asm("fma.rn.f32x2 %0, %1, %2, %3;" : "=l"(d) : "l"(a), "l"(b), "l"(c));
    return d;
}
__device__ __forceinline__ u64 add2(u64 a, u64 b) {
    u64 d;
    asm("add.rn.f32x2 %0, %1, %2;" : "=l"(d) : "l"(a), "l"(b));
    return d;
}
__device__ __forceinline__ u64 pack2(float lo, float hi) {
    u64 r;
    asm("mov.b64 %0, {%1, %2};" : "=l"(r) : "f"(lo), "f"(hi));
    return r;
}
__device__ __forceinline__ void unpack2(u64 x, float& lo, float& hi) {
    asm("mov.b64 {%0, %1}, %2;" : "=f"(lo), "=f"(hi) : "l"(x));
}
__device__ __forceinline__ u64 relu2(u64 x) {
    float lo, hi;
    unpack2(x, lo, hi);
    return pack2(fmaxf(lo, 0.0f), fmaxf(hi, 0.0f));
}

// ---------------------------------------------------------------------------
// software grid barrier (threadFenceReduction pattern)
// ---------------------------------------------------------------------------
__device__ __forceinline__ void barrier_arrive(unsigned* ctr) {
    __threadfence();
    __syncthreads();
    if (threadIdx.x == 0) atomicAdd(ctr, 1u);
}
__device__ __forceinline__ void barrier_wait(unsigned* ctr, unsigned target) {
    if (threadIdx.x == 0) {
        while (*(volatile unsigned*)ctr < target) { __nanosleep(64); }
    }
    __syncthreads();
    __threadfence();
}

// ---------------------------------------------------------------------------
// bitonic compare-select for element at global position i (descending).
// ---------------------------------------------------------------------------
__device__ __forceinline__ u64 cmpsel(u64 v, u64 pv, int i, int k, int j) {
    bool keep_max = (((i & k) == 0) == ((i & j) == 0));
    u64 mx = v > pv ? v : pv;
    u64 mn = v > pv ? pv : v;
    return keep_max ? mx : mn;
}

// sort 1024 keys descending with 256 threads, 4 elems/thread
// (thread t holds i = t + 256m). Emits top-64 to out.
__device__ void sort1024_top64(const u64* __restrict__ in, u64* __restrict__ out,
                               u64* s /* smem[1024] */, int t)
{
    u64 v[4];
#pragma unroll
    for (int m = 0; m < 4; m++) v[m] = in[t + 256 * m];

    for (int k = 2; k <= 1024; k <<= 1) {
        for (int j = k >> 1; j > 0; j >>= 1) {
            if (j >= 256) {
                int h = j >> 8;   // 1 or 2
#pragma unroll
                for (int m = 0; m < 4; m++) {
                    if (!(m & h)) {
                        int mp = m | h;
                        int i = t + (m << 8);
                        bool keep_max = ((i & k) == 0);
                        u64 a = v[m], b = v[mp];
                        u64 mx = a > b ? a : b;
                        u64 mn = a > b ? b : a;
                        v[m]  = keep_max ? mx : mn;
                        v[mp] = keep_max ? mn : mx;
                    }
                }
            } else if (j >= 32) {
                __syncthreads();
#pragma unroll
                for (int m = 0; m < 4; m++) s[t + 256 * m] = v[m];
                __syncthreads();
#pragma unroll
                for (int m = 0; m < 4; m++) {
                    int i = t + 256 * m;
                    v[m] = cmpsel(v[m], s[i ^ j], i, k, j);
                }
            } else {
#pragma unroll
                for (int m = 0; m < 4; m++) {
                    int i = t + 256 * m;
                    u64 pv = __shfl_xor_sync(0xffffffffu, v[m], j);
                    v[m] = cmpsel(v[m], pv, i, k, j);
                }
            }
        }
    }
    __syncthreads();   // protect s reuse by caller
    if (t < KKEY) out[t] = v[0];   // elements 0..63 (descending)
}

// ---------------------------------------------------------------------------
// ONE fused kernel: score -> gbar -> 64x sort1024 -> gbar -> 4x sort1024
// -> gbar -> final 256-sort + gather
// ---------------------------------------------------------------------------
__global__ __launch_bounds__(NT) void fused_kernel(
    const float* __restrict__ src,
    const float* __restrict__ W1, const float* __restrict__ b1,
    const float* __restrict__ W2, const float* __restrict__ b2,
    const float* __restrict__ Wa, const float* __restrict__ ba,
    const float* __restrict__ Wb, const float* __restrict__ bb_,
    const float* __restrict__ Wc, const float* __restrict__ bc,
    float* __restrict__ out)
{
    // score-phase weights (dup'd into both f32 halves); Wa transposed
    __shared__ __align__(16) u64 sW1[192];
    __shared__ __align__(16) u64 sW2[2048];
    __shared__ __align__(16) u64 sWaT[1024];
    __shared__ __align__(16) u64 sWb[128];
    __shared__ __align__(16) u64 sWc[8];
    __shared__ u64 sb1[32];
    __shared__ u64 sb2[64];
    __shared__ u64 sba[16];
    __shared__ u64 sbb[8];
    __shared__ u64 sbc;
    __shared__ u64 s_sort[1024];
    __shared__ int sidx[KKEY];

    const int t = threadIdx.x;
    const int blk = blockIdx.x;

    // ---------------- phase 1: score (all 128 blocks) ----------------
#define DUP(w) ( ((u64)__float_as_uint(w)) * 0x100000001ULL )
    for (int i = t; i < 2048; i += NT) sW2[i] = DUP(W2[i]);
    for (int idx = t; idx < 1024; idx += NT) {
        int j = idx >> 4, i = idx & 15;
        sWaT[idx] = DUP(Wa[i * 64 + j]);
    }
    if (t < 192) sW1[t] = DUP(W1[t]);
    if (t < 128) sWb[t] = DUP(Wb[t]);
    if (t < 64)  sb2[t] = DUP(b2[t]);
    if (t < 32)  sb1[t] = DUP(b1[t]);
    if (t < 16)  sba[t] = DUP(ba[t]);
    if (t < 8)   sbb[t] = DUP(bb_[t]);
    if (t < 8)   sWc[t] = DUP(Wc[t]);
    if (t == 0)  sbc = DUP(bc[0]);
#undef DUP
    __syncthreads();

    {
        const int gid = blk * NT + t;    // pair id
        const int n0 = 2 * gid;          // points n0, n0+1

        u64 x[6];
#pragma unroll
        for (int c = 0; c < 6; c++) {
            float2 v = *(const float2*)(src + c * N_PTS + n0);
            x[c] = pack2(v.x, v.y);
        }

        // layer 1: 6 -> 32, relu
        u64 h1[32];
#pragma unroll
        for (int i = 0; i < 32; i++) {
            const ulonglong2* w = (const ulonglong2*)(sW1 + i * 6);
            ulonglong2 p0 = w[0], p1 = w[1], p2 = w[2];
            u64 v = sb1[i];
            v = fma2(p0.x, x[0], v);
            v = fma2(p0.y, x[1], v);
            v = fma2(p1.x, x[2], v);
            v = fma2(p1.y, x[3], v);
            v = fma2(p2.x, x[4], v);
            v = fma2(p2.y, x[5], v);
            h1[i] = relu2(v);
        }

        // layer 2 (32->64, relu) fused with layer a (64->16)
        u64 a[16];
#pragma unroll
        for (int i = 0; i < 16; i++) a[i] = sba[i];

#pragma unroll 2
        for (int j = 0; j < 64; j++) {
            const ulonglong2* w2 = (const ulonglong2*)(sW2 + j * 32);
            u64 a0 = sb2[j], a1 = 0ULL, a2 = 0ULL, a3 = 0ULL;
#pragma unroll
            for (int k = 0; k < 32; k += 4) {
                ulonglong2 p0 = w2[k / 2];
                ulonglong2 p1 = w2[k / 2 + 1];
                a0 = fma2(p0.x, h1[k],     a0);
                a1 = fma2(p0.y, h1[k + 1], a1);
                a2 = fma2(p1.x, h1[k + 2], a2);
                a3 = fma2(p1.y, h1[k + 3], a3);
            }
            u64 v = relu2(add2(add2(a0, a1), add2(a2, a3)));

            const ulonglong2* wa = (const ulonglong2*)(sWaT + j * 16);
#pragma unroll
            for (int i = 0; i < 16; i += 2) {
                ulonglong2 p = wa[i / 2];
                a[i]     = fma2(p.x, v, a[i]);
                a[i + 1] = fma2(p.y, v, a[i + 1]);
            }
        }
#pragma unroll
        for (int i = 0; i < 16; i++) a[i] = relu2(a[i]);

        // layer b: 16 -> 8, relu
        u64 hb[8];
#pragma unroll
        for (int i = 0; i < 8; i++) {
            const ulonglong2* wb = (const ulonglong2*)(sWb + i * 16);
            u64 s0 = sbb[i], s1 = 0ULL;
#pragma unroll
            for (int k = 0; k < 16; k += 4) {
                ulonglong2 p0 = wb[k / 2];
                ulonglong2 p1 = wb[k / 2 + 1];
                s0 = fma2(p0.x, a[k],     s0);
                s1 = fma2(p0.y, a[k + 1], s1);
                s0 = fma2(p1.x, a[k + 2], s0);
                s1 = fma2(p1.y, a[k + 3], s1);
            }
            hb[i] = relu2(add2(s0, s1));
        }

        // layer c: 8 -> 1, softplus
        u64 c2 = sbc;
#pragma unroll
        for (int k = 0; k < 8; k++) c2 = fma2(sWc[k], hb[k], c2);
        float c0, c1;
        unpack2(c2, c0, c1);
        float sp0 = fmaxf(c0, 0.0f) + log1pf(expf(-fabsf(c0)));
        float sp1 = fmaxf(c1, 0.0f) + log1pf(expf(-fabsf(c1)));

        ulonglong2 kk;
        kk.x = ((u64)__float_as_uint(sp0) << 32) | (unsigned int)(~n0);
        kk.y = ((u64)__float_as_uint(sp1) << 32) | (unsigned int)(~(n0 + 1));
        *(ulonglong2*)&g_keys[n0] = kk;
    }

    // ---------------- barrier 1 (all 128) ----------------
    barrier_arrive(&g_ctr1);
    if (blk >= 64) return;
    barrier_wait(&g_ctr1, GRID);

    // ---------------- phase 2: blocks 0..63 sort their 1024 ----------------
    sort1024_top64(g_keys + blk * 1024, g_cand + blk * KKEY, s_sort, t);

    // ---------------- barrier 2 (64 blocks) ----------------
    barrier_arrive(&g_ctr2);
    if (blk >= 4) return;
    barrier_wait(&g_ctr2, 64u);

    // ---------------- phase 3: blocks 0..3 sort 1024 cands ----------------
    sort1024_top64(g_cand + blk * 1024, g_cand2 + blk * KKEY, s_sort, t);

    // ---------------- barrier 3 (4 blocks) ----------------
    barrier_arrive(&g_ctr3);
    if (blk >= 1) return;
    barrier_wait(&g_ctr3, 4u);

    // ---------------- phase 4: block 0 sorts 256 + gather ----------------
    {
        u64 v = g_cand2[t];
#pragma unroll
        for (int k = 2; k <= 256; k <<= 1) {
            const bool dir_desc = ((t & k) == 0);
#pragma unroll
            for (int j = k >> 1; j > 0; j >>= 1) {
                u64 v2;
                if (j >= 32) {
                    __syncthreads();
                    s_sort[t] = v;
                    __syncthreads();
                    v2 = s_sort[t ^ j];
                } else {
                    v2 = __shfl_xor_sync(0xffffffffu, v, j);
                }
                const bool iLow = ((t & j) == 0);
                const bool keep_max = (dir_desc == iLow);
                v = keep_max ? (v > v2 ? v : v2) : (v < v2 ? v : v2);
            }
        }

        if (t < KKEY) sidx[t] = (int)(~(unsigned int)v);
        __syncthreads();

        // out shape (8, 64, 6) row-major; 3072 elements
#pragma unroll
        for (int o = t; o < 8 * KKEY * 6; o += NT) {
            int c = o % 6;
            int k = (o / 6) & (KKEY - 1);
            int b = o / (6 * KKEY);
            out[o] = src[(b * 6 + c) * N_PTS + sidx[k]];
        }

        // reset counters for the next (graph-replayed) run; block 0 is last
        __syncthreads();
        if (t == 0) { g_ctr1 = 0u; g_ctr2 = 0u; g_ctr3 = 0u; }
    }
}

// ---------------------------------------------------------------------------
extern "C" void kernel_launch(void* const* d_in, const int* in_sizes, int n_in,
                              void* d_out, int out_size)
{
    const float* src = (const float*)d_in[0];   // src_pts (8,6,65536)
    // d_in[1] = tgt_pts (unused)
    const float* W1 = (const float*)d_in[2];
    const float* b1 = (const float*)d_in[3];
    const float* W2 = (const float*)d_in[4];
    const float* b2 = (const float*)d_in[5];
    const float* Wa = (const float*)d_in[6];
    const float* ba = (const float*)d_in[7];
    const float* Wb = (const float*)d_in[8];
    const float* bb = (const float*)d_in[9];
    const float* Wc = (const float*)d_in[10];
    const float* bc = (const float*)d_in[11];
    float* out = (float*)d_out;

    fused_kernel<<<GRID, NT>>>(src, W1, b1, W2, b2, Wa, ba, Wb, bb, Wc, bc, out);
}

// round 8
// speedup vs baseline: 1.3884x; 1.3884x over previous
#include <cuda_runtime.h>
#include <math.h>

#define N_PTS 65536
#define KKEY 64
#define NT_SCORE 256
#define GRID_SCORE 128

typedef unsigned long long u64;

// scratch (no allocations allowed) — referenced ONLY from device code
__device__ u64 g_cand[GRID_SCORE * KKEY];   // 8192
__device__ u64 g_cand2[8 * KKEY];           // 512

// ---------------------------------------------------------------------------
// packed f32x2 helpers (FFMA2: 2 fp32 FMAs per instruction, only via PTX)
// ---------------------------------------------------------------------------
__device__ __forceinline__ u64 fma2(u64 a, u64 b, u64 c) {
    u64 d;
    asm("fma.rn.f32x2 %0, %1, %2, %3;" : "=l"(d) : "l"(a), "l"(b), "l"(c));
    return d;
}
__device__ __forceinline__ u64 add2(u64 a, u64 b) {
    u64 d;
    asm("add.rn.f32x2 %0, %1, %2;" : "=l"(d) : "l"(a), "l"(b));
    return d;
}
__device__ __forceinline__ u64 pack2(float lo, float hi) {
    u64 r;
    asm("mov.b64 %0, {%1, %2};" : "=l"(r) : "f"(lo), "f"(hi));
    return r;
}
__device__ __forceinline__ void unpack2(u64 x, float& lo, float& hi) {
    asm("mov.b64 {%0, %1}, %2;" : "=f"(lo), "=f"(hi) : "l"(x));
}
__device__ __forceinline__ u64 relu2(u64 x) {
    float lo, hi;
    unpack2(x, lo, hi);
    return pack2(fmaxf(lo, 0.0f), fmaxf(hi, 0.0f));
}

// ---------------------------------------------------------------------------
// bitonic compare-select for element at global position i (descending sort).
// Keys unique (low bits = ~index) so strict compare is fine.
// ---------------------------------------------------------------------------
__device__ __forceinline__ u64 cmpsel(u64 v, u64 pv, int i, int k, int j) {
    bool keep_max = (((i & k) == 0) == ((i & j) == 0));
    u64 mx = v > pv ? v : pv;
    u64 mn = v > pv ? pv : v;
    return keep_max ? mx : mn;
}

// sort 512 keys descending: 256 threads, 2 elems/thread (positions t, t+256).
// j>=256 in-thread; 32<=j<=128 via smem; j<32 via shfl.
__device__ __forceinline__ void sort512(u64& v0, u64& v1, u64* s, int t) {
#pragma unroll
    for (int k = 2; k <= 512; k <<= 1) {
#pragma unroll
        for (int j = k >> 1; j > 0; j >>= 1) {
            if (j >= 256) {
                bool keep_max = ((t & k) == 0);
                u64 mx = v0 > v1 ? v0 : v1;
                u64 mn = v0 > v1 ? v1 : v0;
                v0 = keep_max ? mx : mn;
                v1 = keep_max ? mn : mx;
            } else if (j >= 32) {
                __syncthreads();
                s[t] = v0;
                s[t + 256] = v1;
                __syncthreads();
                u64 p0 = s[t ^ j];
                u64 p1 = s[(t + 256) ^ j];
                v0 = cmpsel(v0, p0, t, k, j);
                v1 = cmpsel(v1, p1, t + 256, k, j);
            } else {
                u64 p0 = __shfl_xor_sync(0xffffffffu, v0, j);
                u64 p1 = __shfl_xor_sync(0xffffffffu, v1, j);
                v0 = cmpsel(v0, p0, t, k, j);
                v1 = cmpsel(v1, p1, t + 256, k, j);
            }
        }
    }
}

// ---------------------------------------------------------------------------
// Kernel 1: per-point MLP score (batch 0 only), 2 points/thread via f32x2,
// then in-block sort of the block's 512 keys -> emit block top-64.
// key = (bits(softplus) << 32) | ~n  (sp > 0 so bits are order-monotonic)
// ---------------------------------------------------------------------------
__global__ __launch_bounds__(NT_SCORE) void score_kernel(
    const float* __restrict__ src,
    const float* __restrict__ W1, const float* __restrict__ b1,
    const float* __restrict__ W2, const float* __restrict__ b2,
    const float* __restrict__ Wa, const float* __restrict__ ba,
    const float* __restrict__ Wb, const float* __restrict__ bb_,
    const float* __restrict__ Wc, const float* __restrict__ bc)
{
    // weights duplicated into both f32 halves of a u64; Wa stored transposed
    __shared__ __align__(16) u64 sW1[192];
    __shared__ __align__(16) u64 sW2[2048];
    __shared__ __align__(16) u64 sWaT[1024];
    __shared__ __align__(16) u64 sWb[128];
    __shared__ __align__(16) u64 sWc[8];
    __shared__ u64 sb1[32];
    __shared__ u64 sb2[64];
    __shared__ u64 sba[16];
    __shared__ u64 sbb[8];
    __shared__ u64 sbc;
    __shared__ u64 s_sort[512];

    const int t = threadIdx.x;
    const int blk = blockIdx.x;

#define DUP(w) ( ((u64)__float_as_uint(w)) * 0x100000001ULL )
    for (int i = t; i < 2048; i += NT_SCORE) sW2[i] = DUP(W2[i]);
    for (int idx = t; idx < 1024; idx += NT_SCORE) {
        int j = idx >> 4, i = idx & 15;
        sWaT[idx] = DUP(Wa[i * 64 + j]);
    }
    if (t < 192) sW1[t] = DUP(W1[t]);
    if (t < 128) sWb[t] = DUP(Wb[t]);
    if (t < 64)  sb2[t] = DUP(b2[t]);
    if (t < 32)  sb1[t] = DUP(b1[t]);
    if (t < 16)  sba[t] = DUP(ba[t]);
    if (t < 8)   sbb[t] = DUP(bb_[t]);
    if (t < 8)   sWc[t] = DUP(Wc[t]);
    if (t == 0)  sbc = DUP(bc[0]);
#undef DUP
    __syncthreads();

    const int gid = blk * NT_SCORE + t;   // pair id
    const int n0 = 2 * gid;               // points n0, n0+1

    u64 x[6];
#pragma unroll
    for (int c = 0; c < 6; c++) {
        float2 v = *(const float2*)(src + c * N_PTS + n0);
        x[c] = pack2(v.x, v.y);
    }

    // layer 1: 6 -> 32, relu
    u64 h1[32];
#pragma unroll
    for (int i = 0; i < 32; i++) {
        const ulonglong2* w = (const ulonglong2*)(sW1 + i * 6);
        ulonglong2 p0 = w[0], p1 = w[1], p2 = w[2];
        u64 v = sb1[i];
        v = fma2(p0.x, x[0], v);
        v = fma2(p0.y, x[1], v);
        v = fma2(p1.x, x[2], v);
        v = fma2(p1.y, x[3], v);
        v = fma2(p2.x, x[4], v);
        v = fma2(p2.y, x[5], v);
        h1[i] = relu2(v);
    }

    // layer 2 (32->64, relu) fused with layer a (64->16) accumulation
    u64 a[16];
#pragma unroll
    for (int i = 0; i < 16; i++) a[i] = sba[i];

#pragma unroll 2
    for (int j = 0; j < 64; j++) {
        const ulonglong2* w2 = (const ulonglong2*)(sW2 + j * 32);
        u64 a0 = sb2[j], a1 = 0ULL, a2 = 0ULL, a3 = 0ULL;
#pragma unroll
        for (int k = 0; k < 32; k += 4) {
            ulonglong2 p0 = w2[k / 2];
            ulonglong2 p1 = w2[k / 2 + 1];
            a0 = fma2(p0.x, h1[k],     a0);
            a1 = fma2(p0.y, h1[k + 1], a1);
            a2 = fma2(p1.x, h1[k + 2], a2);
            a3 = fma2(p1.y, h1[k + 3], a3);
        }
        u64 v = relu2(add2(add2(a0, a1), add2(a2, a3)));

        const ulonglong2* wa = (const ulonglong2*)(sWaT + j * 16);
#pragma unroll
        for (int i = 0; i < 16; i += 2) {
            ulonglong2 p = wa[i / 2];
            a[i]     = fma2(p.x, v, a[i]);
            a[i + 1] = fma2(p.y, v, a[i + 1]);
        }
    }
#pragma unroll
    for (int i = 0; i < 16; i++) a[i] = relu2(a[i]);

    // layer b: 16 -> 8, relu
    u64 hb[8];
#pragma unroll
    for (int i = 0; i < 8; i++) {
        const ulonglong2* wb = (const ulonglong2*)(sWb + i * 16);
        u64 s0 = sbb[i], s1 = 0ULL;
#pragma unroll
        for (int k = 0; k < 16; k += 4) {
            ulonglong2 p0 = wb[k / 2];
            ulonglong2 p1 = wb[k / 2 + 1];
            s0 = fma2(p0.x, a[k],     s0);
            s1 = fma2(p0.y, a[k + 1], s1);
            s0 = fma2(p1.x, a[k + 2], s0);
            s1 = fma2(p1.y, a[k + 3], s1);
        }
        hb[i] = relu2(add2(s0, s1));
    }

    // layer c: 8 -> 1, softplus = max(x,0)+log1p(exp(-|x|))
    u64 c2 = sbc;
#pragma unroll
    for (int k = 0; k < 8; k++) c2 = fma2(sWc[k], hb[k], c2);
    float c0, c1;
    unpack2(c2, c0, c1);
    float sp0 = fmaxf(c0, 0.0f) + log1pf(expf(-fabsf(c0)));
    float sp1 = fmaxf(c1, 0.0f) + log1pf(expf(-fabsf(c1)));

    u64 v0 = ((u64)__float_as_uint(sp0) << 32) | (unsigned int)(~n0);
    u64 v1 = ((u64)__float_as_uint(sp1) << 32) | (unsigned int)(~(n0 + 1));

    // in-block selection: sort this block's 512 keys, keep top-64
    sort512(v0, v1, s_sort, t);
    if (t < KKEY) g_cand[blk * KKEY + t] = v0;
}

// ---------------------------------------------------------------------------
// Stage: 8 blocks, each sorts 1024 of the 8192 candidates (descending),
// emits its top-64 -> 512 survivors. 512 threads, 2 elems/thread.
// ---------------------------------------------------------------------------
__global__ __launch_bounds__(512) void stage_kernel()
{
    __shared__ u64 s[1024];
    const int t = threadIdx.x;
    const u64* p = g_cand + blockIdx.x * 1024;

    u64 v0 = p[t];
    u64 v1 = p[t + 512];

#pragma unroll
    for (int k = 2; k <= 1024; k <<= 1) {
#pragma unroll
        for (int j = k >> 1; j > 0; j >>= 1) {
            if (j >= 512) {
                bool keep_max = ((t & k) == 0);
                u64 mx = v0 > v1 ? v0 : v1;
                u64 mn = v0 > v1 ? v1 : v0;
                v0 = keep_max ? mx : mn;
                v1 = keep_max ? mn : mx;
            } else if (j >= 32) {
                __syncthreads();
                s[t] = v0;
                s[t + 512] = v1;
                __syncthreads();
                u64 p0 = s[t ^ j];
                u64 p1 = s[(t + 512) ^ j];
                v0 = cmpsel(v0, p0, t, k, j);
                v1 = cmpsel(v1, p1, t + 512, k, j);
            } else {
                u64 p0 = __shfl_xor_sync(0xffffffffu, v0, j);
                u64 p1 = __shfl_xor_sync(0xffffffffu, v1, j);
                v0 = cmpsel(v0, p0, t, k, j);
                v1 = cmpsel(v1, p1, t + 512, k, j);
            }
        }
    }

    if (t < KKEY) g_cand2[blockIdx.x * KKEY + t] = v0;
}

// ---------------------------------------------------------------------------
// Final: 1 block, 256 threads: sort the 512 survivors, take top-64 indices,
// fused gather: out[b,k,c] = src_pts[b, c, idx[k]]   (B=8, K=64, C=6)
// ---------------------------------------------------------------------------
__global__ __launch_bounds__(256) void final_kernel(
    const float* __restrict__ src, float* __restrict__ out)
{
    __shared__ u64 s_sort[512];
    __shared__ int sidx[KKEY];
    const int t = threadIdx.x;

    u64 v0 = g_cand2[t];
    u64 v1 = g_cand2[t + 256];

    sort512(v0, v1, s_sort, t);

    if (t < KKEY) sidx[t] = (int)(~(unsigned int)v0);
    __syncthreads();

    // out shape (8, 64, 6) row-major; 3072 elements
#pragma unroll
    for (int o = t; o < 8 * KKEY * 6; o += 256) {
        int c = o % 6;
        int k = (o / 6) & (KKEY - 1);
        int b = o / (6 * KKEY);
        out[o] = src[(b * 6 + c) * N_PTS + sidx[k]];
    }
}

// ---------------------------------------------------------------------------
extern "C" void kernel_launch(void* const* d_in, const int* in_sizes, int n_in,
                              void* d_out, int out_size)
{
    const float* src = (const float*)d_in[0];   // src_pts (8,6,65536)
    // d_in[1] = tgt_pts (unused)
    const float* W1 = (const float*)d_in[2];
    const float* b1 = (const float*)d_in[3];
    const float* W2 = (const float*)d_in[4];
    const float* b2 = (const float*)d_in[5];
    const float* Wa = (const float*)d_in[6];
    const float* ba = (const float*)d_in[7];
    const float* Wb = (const float*)d_in[8];
    const float* bb = (const float*)d_in[9];
    const float* Wc = (const float*)d_in[10];
    const float* bc = (const float*)d_in[11];
    float* out = (float*)d_out;

    score_kernel<<<GRID_SCORE, NT_SCORE>>>(
        src, W1, b1, W2, b2, Wa, ba, Wb, bb, Wc, bc);
    stage_kernel<<<8, 512>>>();
    final_kernel<<<1, 256>>>(src, out);
}